// round 10
// baseline (speedup 1.0000x reference)
#include <cuda_runtime.h>
#include <math.h>

// Problem constants
#define S    2048
#define Hdim 4096
#define NH   32
#define HD   128
#define QKV3 12288            // 3*Hdim
#define HSTRIDE 384           // 3*HD per head inside a qkv row

// Scratch (device globals; no runtime allocation)
__device__ float g_qkv[(size_t)S * QKV3];            // 100 MB
__device__ float g_ctx[(size_t)S * Hdim];            // 33 MB

// ---------------------------------------------------------------------------
// tf32 helpers
// ---------------------------------------------------------------------------
__device__ __forceinline__ float to_tf32(float x) {
    unsigned r;
    asm("cvt.rna.tf32.f32 %0, %1;" : "=r"(r) : "f"(x));
    return __uint_as_float(r);
}

__device__ __forceinline__ void mma8(float c[4], const float4& a, const float2& b) {
    asm volatile(
        "mma.sync.aligned.m16n8k8.row.col.f32.tf32.tf32.f32 "
        "{%0,%1,%2,%3},{%4,%5,%6,%7},{%8,%9},{%0,%1,%2,%3};\n"
        : "+f"(c[0]), "+f"(c[1]), "+f"(c[2]), "+f"(c[3])
        : "r"(__float_as_uint(a.x)), "r"(__float_as_uint(a.y)),
          "r"(__float_as_uint(a.z)), "r"(__float_as_uint(a.w)),
          "r"(__float_as_uint(b.x)), "r"(__float_as_uint(b.y)));
}

// Shared-tile layouts:
//  A-frag: As4[kb][p][c] : float4 = (A[m1][k], A[m1+8][k], A[m1][k+4], A[m1+8][k+4])
//          k = kb*8+c, m1 = ((p>>3)<<4)+(p&7)
//  B-frag: Bs2[kb][n][c] : float2 = (B[n][k], B[n][k+4]), k = kb*8+c

// ---------------------------------------------------------------------------
// NT GEMM, double-buffered: C[m,n] = sum_k A[m,k]*B[n,k] + bias[n]
// 128x128 tile, BK=32, 256 threads. One __syncthreads per K-chunk:
//   store(c) -> barrier -> prefetch LDG(c+1) -> mma(c)
// Store targets buf[c&1]; mma(c) reads buf[c&1]; the next store (c+1) goes to
// the other buffer, so cross-warp store/mma overlap is safe with one barrier.
// Dynamic smem 64KB (2 stages x (16KB A + 16KB B)).
// ---------------------------------------------------------------------------
__global__ __launch_bounds__(256) void gemm_tc_nt(
    const float* __restrict__ A, const float* __restrict__ B,
    const float* __restrict__ bias, float* __restrict__ C,
    int K, int lda, int ldb, int ldc)
{
    extern __shared__ char smemraw[];

    const int tid = threadIdx.x, lane = tid & 31, wid = tid >> 5;
    const int warp_m = wid & 1, warp_n = wid >> 1;
    const int t4 = lane >> 2, c4 = lane & 3;

    const int kbA = tid & 3, pA = tid >> 2;
    const int m1  = ((pA >> 3) << 4) + (pA & 7);

    const float* a1p = A + (size_t)(blockIdx.y * 128 + m1) * lda + kbA * 8;
    const float* a2p = a1p + (size_t)8 * lda;
    const float* b1p = B + (size_t)(blockIdx.x * 128 + pA) * ldb + kbA * 8;
    const float* b2p = b1p + (size_t)64 * ldb;

    float acc[4][4][4];
#pragma unroll
    for (int i = 0; i < 4; i++)
#pragma unroll
        for (int j = 0; j < 4; j++)
#pragma unroll
            for (int r = 0; r < 4; r++) acc[i][j][r] = 0.f;

    float4 xa0, xa1, ya0, ya1, u0, u1, v0, v1;
    // prefetch chunk 0
    xa0 = *(const float4*)(a1p);     xa1 = *(const float4*)(a1p + 4);
    ya0 = *(const float4*)(a2p);     ya1 = *(const float4*)(a2p + 4);
    u0  = *(const float4*)(b1p);     u1  = *(const float4*)(b1p + 4);
    v0  = *(const float4*)(b2p);     v1  = *(const float4*)(b2p + 4);

    int buf = 0;
    for (int k0 = 0; k0 < K; k0 += 32) {
        float4* As4 = (float4*)(smemraw + buf * 32768);           // [4][64][4]
        float2* Bs2 = (float2*)(smemraw + buf * 32768 + 16384);   // [4][128][4]

        // ---- store current chunk (opposite buffer from in-flight mma) ----
        {
            float4* ap = As4 + ((kbA * 64) + pA) * 4;
            ap[0] = make_float4(to_tf32(xa0.x), to_tf32(ya0.x), to_tf32(xa1.x), to_tf32(ya1.x));
            ap[1] = make_float4(to_tf32(xa0.y), to_tf32(ya0.y), to_tf32(xa1.y), to_tf32(ya1.y));
            ap[2] = make_float4(to_tf32(xa0.z), to_tf32(ya0.z), to_tf32(xa1.z), to_tf32(ya1.z));
            ap[3] = make_float4(to_tf32(xa0.w), to_tf32(ya0.w), to_tf32(xa1.w), to_tf32(ya1.w));
            float2* bp = Bs2 + ((kbA * 128) + pA) * 4;
            bp[0] = make_float2(to_tf32(u0.x), to_tf32(u1.x));
            bp[1] = make_float2(to_tf32(u0.y), to_tf32(u1.y));
            bp[2] = make_float2(to_tf32(u0.z), to_tf32(u1.z));
            bp[3] = make_float2(to_tf32(u0.w), to_tf32(u1.w));
            float2* bq = Bs2 + ((kbA * 128) + pA + 64) * 4;
            bq[0] = make_float2(to_tf32(v0.x), to_tf32(v1.x));
            bq[1] = make_float2(to_tf32(v0.y), to_tf32(v1.y));
            bq[2] = make_float2(to_tf32(v0.z), to_tf32(v1.z));
            bq[3] = make_float2(to_tf32(v0.w), to_tf32(v1.w));
        }
        __syncthreads();   // the ONLY barrier per chunk

        // ---- prefetch next chunk (overlaps with mma below) ----
        int kn = k0 + 32;
        if (kn < K) {
            xa0 = *(const float4*)(a1p + kn);     xa1 = *(const float4*)(a1p + kn + 4);
            ya0 = *(const float4*)(a2p + kn);     ya1 = *(const float4*)(a2p + kn + 4);
            u0  = *(const float4*)(b1p + kn);     u1  = *(const float4*)(b1p + kn + 4);
            v0  = *(const float4*)(b2p + kn);     v1  = *(const float4*)(b2p + kn + 4);
        }

        // ---- mma over this chunk ----
#pragma unroll
        for (int kb = 0; kb < 4; kb++) {
            float4 af[4]; float2 bf[4];
#pragma unroll
            for (int mt = 0; mt < 4; mt++)
                af[mt] = As4[(kb * 64 + ((warp_m * 4 + mt) << 3) + t4) * 4 + c4];
#pragma unroll
            for (int nt = 0; nt < 4; nt++)
                bf[nt] = Bs2[(kb * 128 + warp_n * 32 + nt * 8 + t4) * 4 + c4];
#pragma unroll
            for (int mt = 0; mt < 4; mt++)
#pragma unroll
                for (int nt = 0; nt < 4; nt++) mma8(acc[mt][nt], af[mt], bf[nt]);
        }
        buf ^= 1;
    }

#pragma unroll
    for (int mt = 0; mt < 4; mt++) {
        int r0 = blockIdx.y * 128 + warp_m * 64 + mt * 16 + t4;
#pragma unroll
        for (int nt = 0; nt < 4; nt++) {
            int cc = blockIdx.x * 128 + warp_n * 32 + nt * 8 + 2 * c4;
            float b0 = bias[cc], b1 = bias[cc + 1];
            *(float2*)&C[(size_t)r0 * ldc + cc] =
                make_float2(acc[mt][nt][0] + b0, acc[mt][nt][1] + b1);
            *(float2*)&C[(size_t)(r0 + 8) * ldc + cc] =
                make_float2(acc[mt][nt][2] + b0, acc[mt][nt][3] + b1);
        }
    }
}

// ---------------------------------------------------------------------------
// RoPE (in place on q,k slices of g_qkv)
// ---------------------------------------------------------------------------
__global__ void rope_kernel(float* __restrict__ qkv)
{
    int idx = blockIdx.x * blockDim.x + threadIdx.x;
    const int total = S * NH * 16 * 2;
    if (idx >= total) return;

    int i = idx & 15;
    int r = idx >> 4;
    int h = r & 31;
    r >>= 5;
    int which = r & 1;
    int s = r >> 1;

    float inv = powf(10000.0f, -(float)i / 16.0f);
    float ang = (float)s * inv;
    float c, sn;
    sincosf(ang, &sn, &c);

    float* base = qkv + (size_t)s * QKV3 + h * HSTRIDE + which * HD;
    float x1 = base[i];
    float x2 = base[i + 16];
    base[i]      = x1 * c - x2 * sn;
    base[i + 16] = x2 * c + x1 * sn;
}

// ---------------------------------------------------------------------------
// Flash attention v4 (proven in R9, ~170us): 512 threads / 16 warps.
// ---------------------------------------------------------------------------
__global__ __launch_bounds__(512, 1) void flash4(
    const float* __restrict__ qkv, float* __restrict__ ctx)
{
    extern __shared__ char smbase[];
    float4 (*Qs)[64][4]    = (float4 (*)[64][4])(smbase);              // [16][64][4]
    float2 (*Ks)[128][4]   = (float2 (*)[128][4])(smbase + 65536);     // [16][128][4]
    float4 (*Pp)[16][8][4] = (float4 (*)[16][8][4])(smbase + 65536);   // alias of Ks
    float2 (*Vs)[128][4]   = (float2 (*)[128][4])(smbase + 131072);    // [16][128][4]
    float  (*red_m)[2]     = (float (*)[2])(smbase + 196608);          // [128][2]
    float  (*red_s)[2]     = (float (*)[2])(smbase + 197632);          // [128][2]

    const int bi = (int)(gridDim.x - 1 - blockIdx.x);   // heavy tiles first
    const int h  = blockIdx.y;

    const int tid = threadIdx.x, lane = tid & 31, w = tid >> 5;
    const int wr = w >> 1, wh = w & 1;
    const int t4 = lane >> 2, c4 = lane & 3;

    const int kbA = tid & 3, pA = (tid >> 2) & 63;
    const int m1  = ((pA >> 3) << 4) + (pA & 7);
    const int ccq = (tid >> 8) * 2;
    const int dV  = tid & 127, kbV0 = (tid >> 7) & 3;

    const int c_base = (c4 & 1) * 2;
    const int c_hi   = (c4 >> 1) * 2;

    // ---- stage Q once (A-frag layout, tf32) ----
    {
        const float* a1p = qkv + (size_t)(bi * 128 + m1) * QKV3 + h * HSTRIDE;
        const float* a2p = a1p + (size_t)8 * QKV3;
#pragma unroll
        for (int u = 0; u < 2; u++) {
            int cc = ccq + u;
            const float* p1 = a1p + cc * 32 + kbA * 8;
            const float* p2 = a2p + cc * 32 + kbA * 8;
            float4 x0 = *(const float4*)p1, x1 = *(const float4*)(p1 + 4);
            float4 y0 = *(const float4*)p2, y1 = *(const float4*)(p2 + 4);
            int kb = cc * 4 + kbA;
            Qs[kb][pA][0] = make_float4(to_tf32(x0.x), to_tf32(y0.x), to_tf32(x1.x), to_tf32(y1.x));
            Qs[kb][pA][1] = make_float4(to_tf32(x0.y), to_tf32(y0.y), to_tf32(x1.y), to_tf32(y1.y));
            Qs[kb][pA][2] = make_float4(to_tf32(x0.z), to_tf32(y0.z), to_tf32(x1.z), to_tf32(y1.z));
            Qs[kb][pA][3] = make_float4(to_tf32(x0.w), to_tf32(y0.w), to_tf32(x1.w), to_tf32(y1.w));
        }
    }

    float o[8][4];
    float m_run[2] = { -1e30f, -1e30f };
    float l_run[2] = { 0.f, 0.f };
#pragma unroll
    for (int nt = 0; nt < 8; nt++)
#pragma unroll
        for (int r = 0; r < 4; r++) o[nt][r] = 0.f;

    const float scale = 0.08838834764831845f;   // 1/sqrt(128)
    const int r_lo = wr * 16 + t4;
    const int r_hi = r_lo + 8;

    for (int bj = 0; bj <= bi; bj++) {
        // ---- stage K ----
        {
            const float* b1p = qkv + (size_t)(bj * 128 + pA) * QKV3 + h * HSTRIDE + HD;
            const float* b2p = b1p + (size_t)64 * QKV3;
#pragma unroll
            for (int u = 0; u < 2; u++) {
                int cc = ccq + u;
                const float* p1 = b1p + cc * 32 + kbA * 8;
                const float* p2 = b2p + cc * 32 + kbA * 8;
                float4 u0 = *(const float4*)p1, u1 = *(const float4*)(p1 + 4);
                float4 v0 = *(const float4*)p2, v1 = *(const float4*)(p2 + 4);
                int kb = cc * 4 + kbA;
                Ks[kb][pA][0]      = make_float2(to_tf32(u0.x), to_tf32(u1.x));
                Ks[kb][pA][1]      = make_float2(to_tf32(u0.y), to_tf32(u1.y));
                Ks[kb][pA][2]      = make_float2(to_tf32(u0.z), to_tf32(u1.z));
                Ks[kb][pA][3]      = make_float2(to_tf32(u0.w), to_tf32(u1.w));
                Ks[kb][pA + 64][0] = make_float2(to_tf32(v0.x), to_tf32(v1.x));
                Ks[kb][pA + 64][1] = make_float2(to_tf32(v0.y), to_tf32(v1.y));
                Ks[kb][pA + 64][2] = make_float2(to_tf32(v0.z), to_tf32(v1.z));
                Ks[kb][pA + 64][3] = make_float2(to_tf32(v0.w), to_tf32(v1.w));
            }
        }
        // ---- stage V (transposed) ----
        {
            const float* vcol = qkv + (size_t)(bj * 128) * QKV3 + h * HSTRIDE + 2 * HD + dV;
#pragma unroll
            for (int g = 0; g < 4; g++) {
                int kb = g * 4 + kbV0;
                float vv[8];
#pragma unroll
                for (int c = 0; c < 8; c++)
                    vv[c] = vcol[(size_t)(kb * 8 + c) * QKV3];
                Vs[kb][dV][0] = make_float2(to_tf32(vv[0]), to_tf32(vv[4]));
                Vs[kb][dV][1] = make_float2(to_tf32(vv[1]), to_tf32(vv[5]));
                Vs[kb][dV][2] = make_float2(to_tf32(vv[2]), to_tf32(vv[6]));
                Vs[kb][dV][3] = make_float2(to_tf32(vv[3]), to_tf32(vv[7]));
            }
        }
        __syncthreads();   // [S] staging visible

        // ---- Q @ K^T ----
        float sc[8][4];
#pragma unroll
        for (int nt = 0; nt < 8; nt++)
#pragma unroll
            for (int r = 0; r < 4; r++) sc[nt][r] = 0.f;

#pragma unroll
        for (int kb = 0; kb < 16; kb++) {
            float4 af = Qs[kb][wr * 8 + t4][c4];
#pragma unroll
            for (int nt = 0; nt < 8; nt++) {
                float2 bf = Ks[kb][wh * 64 + nt * 8 + t4][c4];
                mma8(sc[nt], af, bf);
            }
        }

        // ---- scale + causal mask ----
        if (bj == bi) {
#pragma unroll
            for (int nt = 0; nt < 8; nt++) {
                int cc = wh * 64 + nt * 8 + 2 * c4;
                sc[nt][0] = (cc     <= r_lo) ? sc[nt][0] * scale : -1e30f;
                sc[nt][1] = (cc + 1 <= r_lo) ? sc[nt][1] * scale : -1e30f;
                sc[nt][2] = (cc     <= r_hi) ? sc[nt][2] * scale : -1e30f;
                sc[nt][3] = (cc + 1 <= r_hi) ? sc[nt][3] * scale : -1e30f;
            }
        } else {
#pragma unroll
            for (int nt = 0; nt < 8; nt++)
#pragma unroll
                for (int r = 0; r < 4; r++) sc[nt][r] *= scale;
        }

        // ---- half-row max -> smem exchange ----
        float p0 = -1e30f, p1 = -1e30f;
#pragma unroll
        for (int nt = 0; nt < 8; nt++) {
            p0 = fmaxf(p0, fmaxf(sc[nt][0], sc[nt][1]));
            p1 = fmaxf(p1, fmaxf(sc[nt][2], sc[nt][3]));
        }
#pragma unroll
        for (int off = 1; off <= 2; off <<= 1) {
            p0 = fmaxf(p0, __shfl_xor_sync(0xffffffffu, p0, off));
            p1 = fmaxf(p1, __shfl_xor_sync(0xffffffffu, p1, off));
        }
        if (c4 == 0) {
            red_m[r_lo][wh] = p0;
            red_m[r_hi][wh] = p1;
        }
        __syncthreads();   // [A] QK reads done + max partials visible

        float M0 = fmaxf(red_m[r_lo][0], red_m[r_lo][1]);
        float M1 = fmaxf(red_m[r_hi][0], red_m[r_hi][1]);
        float mn0 = fmaxf(m_run[0], M0);
        float mn1 = fmaxf(m_run[1], M1);
        float a0 = __expf(m_run[0] - mn0);
        float a1 = __expf(m_run[1] - mn1);
        m_run[0] = mn0;  m_run[1] = mn1;

        // ---- exp + half-row sums ----
        float s0 = 0.f, s1 = 0.f;
#pragma unroll
        for (int nt = 0; nt < 8; nt++) {
            sc[nt][0] = __expf(sc[nt][0] - mn0);
            sc[nt][1] = __expf(sc[nt][1] - mn0);
            sc[nt][2] = __expf(sc[nt][2] - mn1);
            sc[nt][3] = __expf(sc[nt][3] - mn1);
            s0 += sc[nt][0] + sc[nt][1];
            s1 += sc[nt][2] + sc[nt][3];
        }
#pragma unroll
        for (int off = 1; off <= 2; off <<= 1) {
            s0 += __shfl_xor_sync(0xffffffffu, s0, off);
            s1 += __shfl_xor_sync(0xffffffffu, s1, off);
        }
        if (c4 == 0) {
            red_s[r_lo][wh] = s0;
            red_s[r_hi][wh] = s1;
        }

        // ---- write P (tf32) into Pp (= Ks region, free after [A]) ----
#pragma unroll
        for (int nt = 0; nt < 8; nt++) {
            int kb = wh * 8 + nt;
            float* s0p = ((float*)&Pp[wr][kb][t4][c_base]) + c_hi;
            s0p[0] = to_tf32(sc[nt][0]);
            s0p[1] = to_tf32(sc[nt][2]);
            float* s1p = ((float*)&Pp[wr][kb][t4][c_base + 1]) + c_hi;
            s1p[0] = to_tf32(sc[nt][1]);
            s1p[1] = to_tf32(sc[nt][3]);
        }
        __syncthreads();   // [B] P + sum partials visible

        float ts0 = red_s[r_lo][0] + red_s[r_lo][1];
        float ts1 = red_s[r_hi][0] + red_s[r_hi][1];
        l_run[0] = l_run[0] * a0 + ts0;
        l_run[1] = l_run[1] * a1 + ts1;

#pragma unroll
        for (int nt = 0; nt < 8; nt++) {
            o[nt][0] *= a0;  o[nt][1] *= a0;
            o[nt][2] *= a1;  o[nt][3] *= a1;
        }

        // ---- P @ V ----
#pragma unroll
        for (int kb = 0; kb < 16; kb++) {
            float4 af = Pp[wr][kb][t4][c4];
#pragma unroll
            for (int nt = 0; nt < 8; nt++) {
                float2 bf = Vs[kb][wh * 64 + nt * 8 + t4][c4];
                mma8(o[nt], af, bf);
            }
        }
        __syncthreads();   // [C] reads done before next staging
    }

    // ---- epilogue ----
    float inv0 = 1.0f / l_run[0];
    float inv1 = 1.0f / l_run[1];
    int row = bi * 128 + wr * 16 + t4;
#pragma unroll
    for (int nt = 0; nt < 8; nt++) {
        int col = h * HD + wh * 64 + nt * 8 + 2 * c4;
        *(float2*)&ctx[(size_t)row * Hdim + col] =
            make_float2(o[nt][0] * inv0, o[nt][1] * inv0);
        *(float2*)&ctx[(size_t)(row + 8) * Hdim + col] =
            make_float2(o[nt][2] * inv1, o[nt][3] * inv1);
    }
}

// ---------------------------------------------------------------------------
// Launch
// ---------------------------------------------------------------------------
extern "C" void kernel_launch(void* const* d_in, const int* in_sizes, int n_in,
                              void* d_out, int out_size)
{
    const float* hidden  = (const float*)d_in[0];
    // d_in[1] = attention_mask (causal; structure known, unused)
    const float* W_qkv   = (const float*)d_in[2];
    const float* b_qkv   = (const float*)d_in[3];
    const float* W_dense = (const float*)d_in[4];
    const float* b_dense = (const float*)d_in[5];
    float* out = (float*)d_out;

    float *qkv, *ctx;
    cudaGetSymbolAddress((void**)&qkv, g_qkv);
    cudaGetSymbolAddress((void**)&ctx, g_ctx);

    const int gemm_smem = 64 * 1024;
    cudaFuncSetAttribute(gemm_tc_nt, cudaFuncAttributeMaxDynamicSharedMemorySize,
                         gemm_smem);

    // 1) QKV GEMM: [2048,4096] x [12288,4096]^T -> [2048,12288]
    {
        dim3 grid(QKV3 / 128, S / 128);
        gemm_tc_nt<<<grid, 256, gemm_smem>>>(hidden, W_qkv, b_qkv, qkv,
                                             Hdim, Hdim, Hdim, QKV3);
    }

    // 2) RoPE in place on q,k
    {
        int total = S * NH * 16 * 2;
        rope_kernel<<<(total + 255) / 256, 256>>>(qkv);
    }

    // 3-5) Fused flash attention v4 -> ctx [2048, 4096]
    {
        const int smem_bytes = 194 * 1024;
        cudaFuncSetAttribute(flash4, cudaFuncAttributeMaxDynamicSharedMemorySize,
                             smem_bytes);
        dim3 grid(S / 128, NH);
        flash4<<<grid, 512, smem_bytes>>>(qkv, ctx);
    }

    // 6) Dense GEMM: ctx [2048,4096] x W_dense^T -> out
    {
        dim3 grid(Hdim / 128, S / 128);
        gemm_tc_nt<<<grid, 256, gemm_smem>>>(ctx, W_dense, b_dense, out,
                                             Hdim, Hdim, Hdim, Hdim);
    }
}

// round 11
// speedup vs baseline: 1.0055x; 1.0055x over previous
#include <cuda_runtime.h>
#include <math.h>

// Problem constants
#define S    2048
#define Hdim 4096
#define NH   32
#define HD   128
#define QKV3 12288            // 3*Hdim
#define HSTRIDE 384           // 3*HD per head inside a qkv row

// Scratch (device globals; no runtime allocation)
__device__ float g_qkv[(size_t)S * QKV3];            // 100 MB
__device__ float g_ctx[(size_t)S * Hdim];            // 33 MB

// ---------------------------------------------------------------------------
// tf32 helpers
// ---------------------------------------------------------------------------
__device__ __forceinline__ float to_tf32(float x) {
    unsigned r;
    asm("cvt.rna.tf32.f32 %0, %1;" : "=r"(r) : "f"(x));
    return __uint_as_float(r);
}

__device__ __forceinline__ void mma8(float c[4], const float4& a, const float2& b) {
    asm volatile(
        "mma.sync.aligned.m16n8k8.row.col.f32.tf32.tf32.f32 "
        "{%0,%1,%2,%3},{%4,%5,%6,%7},{%8,%9},{%0,%1,%2,%3};\n"
        : "+f"(c[0]), "+f"(c[1]), "+f"(c[2]), "+f"(c[3])
        : "r"(__float_as_uint(a.x)), "r"(__float_as_uint(a.y)),
          "r"(__float_as_uint(a.z)), "r"(__float_as_uint(a.w)),
          "r"(__float_as_uint(b.x)), "r"(__float_as_uint(b.y)));
}

// Shared-tile layouts:
//  A-frag: As4[kb][p][c] : float4 = (A[m1][k], A[m1+8][k], A[m1][k+4], A[m1+8][k+4])
//          k = kb*8+c, m1 = ((p>>3)<<4)+(p&7)
//  B-frag: Bs2[kb][n][c] : float2 = (B[n][k], B[n][k+4]), k = kb*8+c

// ---------------------------------------------------------------------------
// NT GEMM v2: C[m,n] = sum_k A[m,k]*B[n,k] + bias[n]
// Block tile 128(M) x 256(N), BK=32, 256 threads, 8 warps (2x4),
// warp tile 64x64 (acc[4][8][4]) -> 16 flop per smem byte (was 10.7).
// Single-buffer smem (48KB static), register prefetch, 2 barriers/chunk.
// ---------------------------------------------------------------------------
__global__ __launch_bounds__(256, 1) void gemm_tc_nt(
    const float* __restrict__ A, const float* __restrict__ B,
    const float* __restrict__ bias, float* __restrict__ C,
    int K, int lda, int ldb, int ldc)
{
    __shared__ float4 As4[4][64][4];    // 16 KB
    __shared__ float2 Bs2[4][256][4];   // 32 KB

    const int tid = threadIdx.x, lane = tid & 31, wid = tid >> 5;
    const int warp_m = wid & 1, warp_n = wid >> 1;   // 2 x 4 warps
    const int t4 = lane >> 2, c4 = lane & 3;

    const int kbA = tid & 3, pA = tid >> 2;          // A loader: 4 x 64
    const int m1  = ((pA >> 3) << 4) + (pA & 7);

    const float* a1p = A + (size_t)(blockIdx.y * 128 + m1) * lda + kbA * 8;
    const float* a2p = a1p + (size_t)8 * lda;
    const float* b1p = B + (size_t)(blockIdx.x * 256 + pA) * ldb + kbA * 8;  // rows pA+64j

    float acc[4][8][4];
#pragma unroll
    for (int i = 0; i < 4; i++)
#pragma unroll
        for (int j = 0; j < 8; j++)
#pragma unroll
            for (int r = 0; r < 4; r++) acc[i][j][r] = 0.f;

    float4 xa0, xa1, ya0, ya1;
    float4 bu[4][2];
    // prefetch chunk 0
    xa0 = *(const float4*)(a1p);     xa1 = *(const float4*)(a1p + 4);
    ya0 = *(const float4*)(a2p);     ya1 = *(const float4*)(a2p + 4);
#pragma unroll
    for (int j = 0; j < 4; j++) {
        const float* bp = b1p + (size_t)(64 * j) * ldb;
        bu[j][0] = *(const float4*)(bp);
        bu[j][1] = *(const float4*)(bp + 4);
    }

    for (int k0 = 0; k0 < K; k0 += 32) {
        __syncthreads();   // previous mma reads done
        As4[kbA][pA][0] = make_float4(to_tf32(xa0.x), to_tf32(ya0.x), to_tf32(xa1.x), to_tf32(ya1.x));
        As4[kbA][pA][1] = make_float4(to_tf32(xa0.y), to_tf32(ya0.y), to_tf32(xa1.y), to_tf32(ya1.y));
        As4[kbA][pA][2] = make_float4(to_tf32(xa0.z), to_tf32(ya0.z), to_tf32(xa1.z), to_tf32(ya1.z));
        As4[kbA][pA][3] = make_float4(to_tf32(xa0.w), to_tf32(ya0.w), to_tf32(xa1.w), to_tf32(ya1.w));
#pragma unroll
        for (int j = 0; j < 4; j++) {
            float2* bp = &Bs2[kbA][pA + 64 * j][0];
            bp[0] = make_float2(to_tf32(bu[j][0].x), to_tf32(bu[j][1].x));
            bp[1] = make_float2(to_tf32(bu[j][0].y), to_tf32(bu[j][1].y));
            bp[2] = make_float2(to_tf32(bu[j][0].z), to_tf32(bu[j][1].z));
            bp[3] = make_float2(to_tf32(bu[j][0].w), to_tf32(bu[j][1].w));
        }
        __syncthreads();   // chunk staged

        // prefetch next chunk (overlaps mma)
        int kn = k0 + 32;
        if (kn < K) {
            xa0 = *(const float4*)(a1p + kn);     xa1 = *(const float4*)(a1p + kn + 4);
            ya0 = *(const float4*)(a2p + kn);     ya1 = *(const float4*)(a2p + kn + 4);
#pragma unroll
            for (int j = 0; j < 4; j++) {
                const float* bp = b1p + (size_t)(64 * j) * ldb + kn;
                bu[j][0] = *(const float4*)(bp);
                bu[j][1] = *(const float4*)(bp + 4);
            }
        }

        // mma over this chunk: warp tile 64x64
#pragma unroll
        for (int kb = 0; kb < 4; kb++) {
            float4 af[4]; float2 bf[8];
#pragma unroll
            for (int mt = 0; mt < 4; mt++)
                af[mt] = As4[kb][((warp_m * 4 + mt) << 3) + t4][c4];
#pragma unroll
            for (int nt = 0; nt < 8; nt++)
                bf[nt] = Bs2[kb][warp_n * 64 + nt * 8 + t4][c4];
#pragma unroll
            for (int mt = 0; mt < 4; mt++)
#pragma unroll
                for (int nt = 0; nt < 8; nt++) mma8(acc[mt][nt], af[mt], bf[nt]);
        }
    }

#pragma unroll
    for (int mt = 0; mt < 4; mt++) {
        int r0 = blockIdx.y * 128 + warp_m * 64 + mt * 16 + t4;
#pragma unroll
        for (int nt = 0; nt < 8; nt++) {
            int cc = blockIdx.x * 256 + warp_n * 64 + nt * 8 + 2 * c4;
            float b0 = bias[cc], b1 = bias[cc + 1];
            *(float2*)&C[(size_t)r0 * ldc + cc] =
                make_float2(acc[mt][nt][0] + b0, acc[mt][nt][1] + b1);
            *(float2*)&C[(size_t)(r0 + 8) * ldc + cc] =
                make_float2(acc[mt][nt][2] + b0, acc[mt][nt][3] + b1);
        }
    }
}

// ---------------------------------------------------------------------------
// RoPE (in place on q,k slices of g_qkv)
// ---------------------------------------------------------------------------
__global__ void rope_kernel(float* __restrict__ qkv)
{
    int idx = blockIdx.x * blockDim.x + threadIdx.x;
    const int total = S * NH * 16 * 2;
    if (idx >= total) return;

    int i = idx & 15;
    int r = idx >> 4;
    int h = r & 31;
    r >>= 5;
    int which = r & 1;
    int s = r >> 1;

    float inv = powf(10000.0f, -(float)i / 16.0f);
    float ang = (float)s * inv;
    float c, sn;
    sincosf(ang, &sn, &c);

    float* base = qkv + (size_t)s * QKV3 + h * HSTRIDE + which * HD;
    float x1 = base[i];
    float x2 = base[i + 16];
    base[i]      = x1 * c - x2 * sn;
    base[i + 16] = x2 * c + x1 * sn;
}

// ---------------------------------------------------------------------------
// Flash attention v4 (proven, ~170us): 512 threads / 16 warps.
// ---------------------------------------------------------------------------
__global__ __launch_bounds__(512, 1) void flash4(
    const float* __restrict__ qkv, float* __restrict__ ctx)
{
    extern __shared__ char smbase[];
    float4 (*Qs)[64][4]    = (float4 (*)[64][4])(smbase);              // [16][64][4]
    float2 (*Ks)[128][4]   = (float2 (*)[128][4])(smbase + 65536);     // [16][128][4]
    float4 (*Pp)[16][8][4] = (float4 (*)[16][8][4])(smbase + 65536);   // alias of Ks
    float2 (*Vs)[128][4]   = (float2 (*)[128][4])(smbase + 131072);    // [16][128][4]
    float  (*red_m)[2]     = (float (*)[2])(smbase + 196608);          // [128][2]
    float  (*red_s)[2]     = (float (*)[2])(smbase + 197632);          // [128][2]

    const int bi = (int)(gridDim.x - 1 - blockIdx.x);   // heavy tiles first
    const int h  = blockIdx.y;

    const int tid = threadIdx.x, lane = tid & 31, w = tid >> 5;
    const int wr = w >> 1, wh = w & 1;
    const int t4 = lane >> 2, c4 = lane & 3;

    const int kbA = tid & 3, pA = (tid >> 2) & 63;
    const int m1  = ((pA >> 3) << 4) + (pA & 7);
    const int ccq = (tid >> 8) * 2;
    const int dV  = tid & 127, kbV0 = (tid >> 7) & 3;

    const int c_base = (c4 & 1) * 2;
    const int c_hi   = (c4 >> 1) * 2;

    // ---- stage Q once (A-frag layout, tf32) ----
    {
        const float* a1p = qkv + (size_t)(bi * 128 + m1) * QKV3 + h * HSTRIDE;
        const float* a2p = a1p + (size_t)8 * QKV3;
#pragma unroll
        for (int u = 0; u < 2; u++) {
            int cc = ccq + u;
            const float* p1 = a1p + cc * 32 + kbA * 8;
            const float* p2 = a2p + cc * 32 + kbA * 8;
            float4 x0 = *(const float4*)p1, x1 = *(const float4*)(p1 + 4);
            float4 y0 = *(const float4*)p2, y1 = *(const float4*)(p2 + 4);
            int kb = cc * 4 + kbA;
            Qs[kb][pA][0] = make_float4(to_tf32(x0.x), to_tf32(y0.x), to_tf32(x1.x), to_tf32(y1.x));
            Qs[kb][pA][1] = make_float4(to_tf32(x0.y), to_tf32(y0.y), to_tf32(x1.y), to_tf32(y1.y));
            Qs[kb][pA][2] = make_float4(to_tf32(x0.z), to_tf32(y0.z), to_tf32(x1.z), to_tf32(y1.z));
            Qs[kb][pA][3] = make_float4(to_tf32(x0.w), to_tf32(y0.w), to_tf32(x1.w), to_tf32(y1.w));
        }
    }

    float o[8][4];
    float m_run[2] = { -1e30f, -1e30f };
    float l_run[2] = { 0.f, 0.f };
#pragma unroll
    for (int nt = 0; nt < 8; nt++)
#pragma unroll
        for (int r = 0; r < 4; r++) o[nt][r] = 0.f;

    const float scale = 0.08838834764831845f;   // 1/sqrt(128)
    const int r_lo = wr * 16 + t4;
    const int r_hi = r_lo + 8;

    for (int bj = 0; bj <= bi; bj++) {
        // ---- stage K ----
        {
            const float* b1p = qkv + (size_t)(bj * 128 + pA) * QKV3 + h * HSTRIDE + HD;
            const float* b2p = b1p + (size_t)64 * QKV3;
#pragma unroll
            for (int u = 0; u < 2; u++) {
                int cc = ccq + u;
                const float* p1 = b1p + cc * 32 + kbA * 8;
                const float* p2 = b2p + cc * 32 + kbA * 8;
                float4 u0 = *(const float4*)p1, u1 = *(const float4*)(p1 + 4);
                float4 v0 = *(const float4*)p2, v1 = *(const float4*)(p2 + 4);
                int kb = cc * 4 + kbA;
                Ks[kb][pA][0]      = make_float2(to_tf32(u0.x), to_tf32(u1.x));
                Ks[kb][pA][1]      = make_float2(to_tf32(u0.y), to_tf32(u1.y));
                Ks[kb][pA][2]      = make_float2(to_tf32(u0.z), to_tf32(u1.z));
                Ks[kb][pA][3]      = make_float2(to_tf32(u0.w), to_tf32(u1.w));
                Ks[kb][pA + 64][0] = make_float2(to_tf32(v0.x), to_tf32(v1.x));
                Ks[kb][pA + 64][1] = make_float2(to_tf32(v0.y), to_tf32(v1.y));
                Ks[kb][pA + 64][2] = make_float2(to_tf32(v0.z), to_tf32(v1.z));
                Ks[kb][pA + 64][3] = make_float2(to_tf32(v0.w), to_tf32(v1.w));
            }
        }
        // ---- stage V (transposed) ----
        {
            const float* vcol = qkv + (size_t)(bj * 128) * QKV3 + h * HSTRIDE + 2 * HD + dV;
#pragma unroll
            for (int g = 0; g < 4; g++) {
                int kb = g * 4 + kbV0;
                float vv[8];
#pragma unroll
                for (int c = 0; c < 8; c++)
                    vv[c] = vcol[(size_t)(kb * 8 + c) * QKV3];
                Vs[kb][dV][0] = make_float2(to_tf32(vv[0]), to_tf32(vv[4]));
                Vs[kb][dV][1] = make_float2(to_tf32(vv[1]), to_tf32(vv[5]));
                Vs[kb][dV][2] = make_float2(to_tf32(vv[2]), to_tf32(vv[6]));
                Vs[kb][dV][3] = make_float2(to_tf32(vv[3]), to_tf32(vv[7]));
            }
        }
        __syncthreads();   // [S] staging visible

        // ---- Q @ K^T ----
        float sc[8][4];
#pragma unroll
        for (int nt = 0; nt < 8; nt++)
#pragma unroll
            for (int r = 0; r < 4; r++) sc[nt][r] = 0.f;

#pragma unroll
        for (int kb = 0; kb < 16; kb++) {
            float4 af = Qs[kb][wr * 8 + t4][c4];
#pragma unroll
            for (int nt = 0; nt < 8; nt++) {
                float2 bf = Ks[kb][wh * 64 + nt * 8 + t4][c4];
                mma8(sc[nt], af, bf);
            }
        }

        // ---- scale + causal mask ----
        if (bj == bi) {
#pragma unroll
            for (int nt = 0; nt < 8; nt++) {
                int cc = wh * 64 + nt * 8 + 2 * c4;
                sc[nt][0] = (cc     <= r_lo) ? sc[nt][0] * scale : -1e30f;
                sc[nt][1] = (cc + 1 <= r_lo) ? sc[nt][1] * scale : -1e30f;
                sc[nt][2] = (cc     <= r_hi) ? sc[nt][2] * scale : -1e30f;
                sc[nt][3] = (cc + 1 <= r_hi) ? sc[nt][3] * scale : -1e30f;
            }
        } else {
#pragma unroll
            for (int nt = 0; nt < 8; nt++)
#pragma unroll
                for (int r = 0; r < 4; r++) sc[nt][r] *= scale;
        }

        // ---- half-row max -> smem exchange ----
        float p0 = -1e30f, p1 = -1e30f;
#pragma unroll
        for (int nt = 0; nt < 8; nt++) {
            p0 = fmaxf(p0, fmaxf(sc[nt][0], sc[nt][1]));
            p1 = fmaxf(p1, fmaxf(sc[nt][2], sc[nt][3]));
        }
#pragma unroll
        for (int off = 1; off <= 2; off <<= 1) {
            p0 = fmaxf(p0, __shfl_xor_sync(0xffffffffu, p0, off));
            p1 = fmaxf(p1, __shfl_xor_sync(0xffffffffu, p1, off));
        }
        if (c4 == 0) {
            red_m[r_lo][wh] = p0;
            red_m[r_hi][wh] = p1;
        }
        __syncthreads();   // [A] QK reads done + max partials visible

        float M0 = fmaxf(red_m[r_lo][0], red_m[r_lo][1]);
        float M1 = fmaxf(red_m[r_hi][0], red_m[r_hi][1]);
        float mn0 = fmaxf(m_run[0], M0);
        float mn1 = fmaxf(m_run[1], M1);
        float a0 = __expf(m_run[0] - mn0);
        float a1 = __expf(m_run[1] - mn1);
        m_run[0] = mn0;  m_run[1] = mn1;

        // ---- exp + half-row sums ----
        float s0 = 0.f, s1 = 0.f;
#pragma unroll
        for (int nt = 0; nt < 8; nt++) {
            sc[nt][0] = __expf(sc[nt][0] - mn0);
            sc[nt][1] = __expf(sc[nt][1] - mn0);
            sc[nt][2] = __expf(sc[nt][2] - mn1);
            sc[nt][3] = __expf(sc[nt][3] - mn1);
            s0 += sc[nt][0] + sc[nt][1];
            s1 += sc[nt][2] + sc[nt][3];
        }
#pragma unroll
        for (int off = 1; off <= 2; off <<= 1) {
            s0 += __shfl_xor_sync(0xffffffffu, s0, off);
            s1 += __shfl_xor_sync(0xffffffffu, s1, off);
        }
        if (c4 == 0) {
            red_s[r_lo][wh] = s0;
            red_s[r_hi][wh] = s1;
        }

        // ---- write P (tf32) into Pp (= Ks region, free after [A]) ----
#pragma unroll
        for (int nt = 0; nt < 8; nt++) {
            int kb = wh * 8 + nt;
            float* s0p = ((float*)&Pp[wr][kb][t4][c_base]) + c_hi;
            s0p[0] = to_tf32(sc[nt][0]);
            s0p[1] = to_tf32(sc[nt][2]);
            float* s1p = ((float*)&Pp[wr][kb][t4][c_base + 1]) + c_hi;
            s1p[0] = to_tf32(sc[nt][1]);
            s1p[1] = to_tf32(sc[nt][3]);
        }
        __syncthreads();   // [B] P + sum partials visible

        float ts0 = red_s[r_lo][0] + red_s[r_lo][1];
        float ts1 = red_s[r_hi][0] + red_s[r_hi][1];
        l_run[0] = l_run[0] * a0 + ts0;
        l_run[1] = l_run[1] * a1 + ts1;

#pragma unroll
        for (int nt = 0; nt < 8; nt++) {
            o[nt][0] *= a0;  o[nt][1] *= a0;
            o[nt][2] *= a1;  o[nt][3] *= a1;
        }

        // ---- P @ V ----
#pragma unroll
        for (int kb = 0; kb < 16; kb++) {
            float4 af = Pp[wr][kb][t4][c4];
#pragma unroll
            for (int nt = 0; nt < 8; nt++) {
                float2 bf = Vs[kb][wh * 64 + nt * 8 + t4][c4];
                mma8(o[nt], af, bf);
            }
        }
        __syncthreads();   // [C] reads done before next staging
    }

    // ---- epilogue ----
    float inv0 = 1.0f / l_run[0];
    float inv1 = 1.0f / l_run[1];
    int row = bi * 128 + wr * 16 + t4;
#pragma unroll
    for (int nt = 0; nt < 8; nt++) {
        int col = h * HD + wh * 64 + nt * 8 + 2 * c4;
        *(float2*)&ctx[(size_t)row * Hdim + col] =
            make_float2(o[nt][0] * inv0, o[nt][1] * inv0);
        *(float2*)&ctx[(size_t)(row + 8) * Hdim + col] =
            make_float2(o[nt][2] * inv1, o[nt][3] * inv1);
    }
}

// ---------------------------------------------------------------------------
// Launch
// ---------------------------------------------------------------------------
extern "C" void kernel_launch(void* const* d_in, const int* in_sizes, int n_in,
                              void* d_out, int out_size)
{
    const float* hidden  = (const float*)d_in[0];
    // d_in[1] = attention_mask (causal; structure known, unused)
    const float* W_qkv   = (const float*)d_in[2];
    const float* b_qkv   = (const float*)d_in[3];
    const float* W_dense = (const float*)d_in[4];
    const float* b_dense = (const float*)d_in[5];
    float* out = (float*)d_out;

    float *qkv, *ctx;
    cudaGetSymbolAddress((void**)&qkv, g_qkv);
    cudaGetSymbolAddress((void**)&ctx, g_ctx);

    // 1) QKV GEMM: [2048,4096] x [12288,4096]^T -> [2048,12288]
    {
        dim3 grid(QKV3 / 256, S / 128);
        gemm_tc_nt<<<grid, 256>>>(hidden, W_qkv, b_qkv, qkv,
                                  Hdim, Hdim, Hdim, QKV3);
    }

    // 2) RoPE in place on q,k
    {
        int total = S * NH * 16 * 2;
        rope_kernel<<<(total + 255) / 256, 256>>>(qkv);
    }

    // 3-5) Fused flash attention v4 -> ctx [2048, 4096]
    {
        const int smem_bytes = 194 * 1024;
        cudaFuncSetAttribute(flash4, cudaFuncAttributeMaxDynamicSharedMemorySize,
                             smem_bytes);
        dim3 grid(S / 128, NH);
        flash4<<<grid, 512, smem_bytes>>>(qkv, ctx);
    }

    // 6) Dense GEMM: ctx [2048,4096] x W_dense^T -> out
    {
        dim3 grid(Hdim / 256, S / 128);
        gemm_tc_nt<<<grid, 256>>>(ctx, W_dense, b_dense, out,
                                  Hdim, Hdim, Hdim, Hdim);
    }
}

// round 13
// speedup vs baseline: 1.1107x; 1.1046x over previous
#include <cuda_runtime.h>
#include <cuda_fp16.h>
#include <cstdint>
#include <math.h>

// Problem constants
#define S    2048
#define Hdim 4096
#define NH   32
#define HD   128
#define QKV3 12288            // 3*Hdim
#define HSTRIDE 384           // 3*HD per head inside a qkv row

// Scratch (device globals; no runtime allocation)
__device__ float g_qkv[(size_t)S * QKV3];            // 100 MB
__device__ float g_ctx[(size_t)S * Hdim];            // 33 MB

// ---------------------------------------------------------------------------
// helpers
// ---------------------------------------------------------------------------
__device__ __forceinline__ float to_tf32(float x) {
    unsigned r;
    asm("cvt.rna.tf32.f32 %0, %1;" : "=r"(r) : "f"(x));
    return __uint_as_float(r);
}

__device__ __forceinline__ uint32_t f2h2(float a, float b) {
    __half2 h = __floats2half2_rn(a, b);
    return *reinterpret_cast<uint32_t*>(&h);
}

// tf32 m16n8k8 (used by flash4 only)
__device__ __forceinline__ void mma8(float c[4], const float4& a, const float2& b) {
    asm volatile(
        "mma.sync.aligned.m16n8k8.row.col.f32.tf32.tf32.f32 "
        "{%0,%1,%2,%3},{%4,%5,%6,%7},{%8,%9},{%0,%1,%2,%3};\n"
        : "+f"(c[0]), "+f"(c[1]), "+f"(c[2]), "+f"(c[3])
        : "r"(__float_as_uint(a.x)), "r"(__float_as_uint(a.y)),
          "r"(__float_as_uint(a.z)), "r"(__float_as_uint(a.w)),
          "r"(__float_as_uint(b.x)), "r"(__float_as_uint(b.y)));
}

// fp16 m16n8k16 (GEMMs)
__device__ __forceinline__ void mma16(float c[4], const uint4& a, const uint2& b) {
    asm volatile(
        "mma.sync.aligned.m16n8k16.row.col.f32.f16.f16.f32 "
        "{%0,%1,%2,%3},{%4,%5,%6,%7},{%8,%9},{%0,%1,%2,%3};\n"
        : "+f"(c[0]), "+f"(c[1]), "+f"(c[2]), "+f"(c[3])
        : "r"(a.x), "r"(a.y), "r"(a.z), "r"(a.w),
          "r"(b.x), "r"(b.y));
}

// ---------------------------------------------------------------------------
// NT GEMM fp16: C[m,n] = sum_k A[m,k]*B[n,k] + bias[n]
// Block tile 128(M) x 256(N), BK=32 (= 2 blocks of 16 k-elems), 256 threads,
// 8 warps (2x4), warp tile 64x64, acc fp32.
// Fragment smem layouts (k-pair space, kp = k/2):
//  Ah[kb][p][c] : uint4 = (h2 A[m1][kp=c], h2 A[m1+8][c], h2 A[m1][c+4], h2 A[m1+8][c+4])
//                 m1 = ((p>>3)<<4)+(p&7), kp local to the kb-block of 8 pairs
//  Bh[kb][n][c] : uint2 = (h2 B[n][kp=c], h2 B[n][kp=c+4])
// ---------------------------------------------------------------------------
__global__ __launch_bounds__(256, 1) void gemm_fp16(
    const float* __restrict__ A, const float* __restrict__ B,
    const float* __restrict__ bias, float* __restrict__ C,
    int K, int lda, int ldb, int ldc)
{
    __shared__ uint4 Ah[2][64][4];    // 8 KB
    __shared__ uint2 Bh[2][256][4];   // 16 KB

    const int tid = threadIdx.x, lane = tid & 31, wid = tid >> 5;
    const int warp_m = wid & 1, warp_n = wid >> 1;   // 2 x 4 warps
    const int t4 = lane >> 2, c4 = lane & 3;

    const int kbA = tid & 3, pA = tid >> 2;          // A loader: 4 x 64
    const int m1  = ((pA >> 3) << 4) + (pA & 7);
    const int kbh = kbA >> 1, hs = kbA & 1;          // 16-elem block, half select

    const float* a1p = A + (size_t)(blockIdx.y * 128 + m1) * lda + kbA * 8;
    const float* a2p = a1p + (size_t)8 * lda;
    const float* Bp  = B + (size_t)(blockIdx.x * 256 + tid) * ldb;  // one row/thread

    float acc[4][8][4];
#pragma unroll
    for (int i = 0; i < 4; i++)
#pragma unroll
        for (int j = 0; j < 8; j++)
#pragma unroll
            for (int r = 0; r < 4; r++) acc[i][j][r] = 0.f;

    float4 xa0, xa1, ya0, ya1;
    float4 bu[8];
    // prefetch chunk 0
    xa0 = *(const float4*)(a1p);     xa1 = *(const float4*)(a1p + 4);
    ya0 = *(const float4*)(a2p);     ya1 = *(const float4*)(a2p + 4);
#pragma unroll
    for (int i = 0; i < 8; i++) bu[i] = *(const float4*)(Bp + i * 4);

    for (int k0 = 0; k0 < K; k0 += 32) {
        __syncthreads();   // previous mma reads done

        // ---- A: rows m1 / m1+8, 8 elems (4 pairs) -> half of 4 uint4 entries ----
        {
            float xs[8] = { xa0.x, xa0.y, xa0.z, xa0.w, xa1.x, xa1.y, xa1.z, xa1.w };
            float ys[8] = { ya0.x, ya0.y, ya0.z, ya0.w, ya1.x, ya1.y, ya1.z, ya1.w };
#pragma unroll
            for (int i = 0; i < 4; i++) {
                uint32_t lo = f2h2(xs[2 * i], xs[2 * i + 1]);
                uint32_t hi = f2h2(ys[2 * i], ys[2 * i + 1]);
                *(uint2*)((char*)(&Ah[kbh][pA][i]) + hs * 8) = make_uint2(lo, hi);
            }
        }
        // ---- B: row n=tid, 32 elems -> 2 kb blocks x 4 uint2 ----
#pragma unroll
        for (int kb = 0; kb < 2; kb++) {
            const float4* q = bu + kb * 4;
            Bh[kb][tid][0] = make_uint2(f2h2(q[0].x, q[0].y), f2h2(q[2].x, q[2].y));
            Bh[kb][tid][1] = make_uint2(f2h2(q[0].z, q[0].w), f2h2(q[2].z, q[2].w));
            Bh[kb][tid][2] = make_uint2(f2h2(q[1].x, q[1].y), f2h2(q[3].x, q[3].y));
            Bh[kb][tid][3] = make_uint2(f2h2(q[1].z, q[1].w), f2h2(q[3].z, q[3].w));
        }
        __syncthreads();   // chunk staged

        // ---- prefetch next chunk (overlaps mma) ----
        int kn = k0 + 32;
        if (kn < K) {
            xa0 = *(const float4*)(a1p + kn);     xa1 = *(const float4*)(a1p + kn + 4);
            ya0 = *(const float4*)(a2p + kn);     ya1 = *(const float4*)(a2p + kn + 4);
#pragma unroll
            for (int i = 0; i < 8; i++) bu[i] = *(const float4*)(Bp + kn + i * 4);
        }

        // ---- mma: 2 kb-blocks x 32 mma16 ----
#pragma unroll
        for (int kb = 0; kb < 2; kb++) {
            uint4 af[4]; uint2 bf[8];
#pragma unroll
            for (int mt = 0; mt < 4; mt++)
                af[mt] = Ah[kb][((warp_m * 4 + mt) << 3) + t4][c4];
#pragma unroll
            for (int nt = 0; nt < 8; nt++)
                bf[nt] = Bh[kb][warp_n * 64 + nt * 8 + t4][c4];
#pragma unroll
            for (int mt = 0; mt < 4; mt++)
#pragma unroll
                for (int nt = 0; nt < 8; nt++) mma16(acc[mt][nt], af[mt], bf[nt]);
        }
    }

#pragma unroll
    for (int mt = 0; mt < 4; mt++) {
        int r0 = blockIdx.y * 128 + warp_m * 64 + mt * 16 + t4;
#pragma unroll
        for (int nt = 0; nt < 8; nt++) {
            int cc = blockIdx.x * 256 + warp_n * 64 + nt * 8 + 2 * c4;
            float b0 = bias[cc], b1 = bias[cc + 1];
            *(float2*)&C[(size_t)r0 * ldc + cc] =
                make_float2(acc[mt][nt][0] + b0, acc[mt][nt][1] + b1);
            *(float2*)&C[(size_t)(r0 + 8) * ldc + cc] =
                make_float2(acc[mt][nt][2] + b0, acc[mt][nt][3] + b1);
        }
    }
}

// ---------------------------------------------------------------------------
// RoPE (in place on q,k slices of g_qkv)
// ---------------------------------------------------------------------------
__global__ void rope_kernel(float* __restrict__ qkv)
{
    int idx = blockIdx.x * blockDim.x + threadIdx.x;
    const int total = S * NH * 16 * 2;
    if (idx >= total) return;

    int i = idx & 15;
    int r = idx >> 4;
    int h = r & 31;
    r >>= 5;
    int which = r & 1;
    int s = r >> 1;

    float inv = powf(10000.0f, -(float)i / 16.0f);
    float ang = (float)s * inv;
    float c, sn;
    sincosf(ang, &sn, &c);

    float* base = qkv + (size_t)s * QKV3 + h * HSTRIDE + which * HD;
    float x1 = base[i];
    float x2 = base[i + 16];
    base[i]      = x1 * c - x2 * sn;
    base[i + 16] = x2 * c + x1 * sn;
}

// ---------------------------------------------------------------------------
// Flash attention v4 (proven, ~170us): 512 threads / 16 warps. tf32 path.
// ---------------------------------------------------------------------------
__global__ __launch_bounds__(512, 1) void flash4(
    const float* __restrict__ qkv, float* __restrict__ ctx)
{
    extern __shared__ char smbase[];
    float4 (*Qs)[64][4]    = (float4 (*)[64][4])(smbase);              // [16][64][4]
    float2 (*Ks)[128][4]   = (float2 (*)[128][4])(smbase + 65536);     // [16][128][4]
    float4 (*Pp)[16][8][4] = (float4 (*)[16][8][4])(smbase + 65536);   // alias of Ks
    float2 (*Vs)[128][4]   = (float2 (*)[128][4])(smbase + 131072);    // [16][128][4]
    float  (*red_m)[2]     = (float (*)[2])(smbase + 196608);          // [128][2]
    float  (*red_s)[2]     = (float (*)[2])(smbase + 197632);          // [128][2]

    const int bi = (int)(gridDim.x - 1 - blockIdx.x);   // heavy tiles first
    const int h  = blockIdx.y;

    const int tid = threadIdx.x, lane = tid & 31, w = tid >> 5;
    const int wr = w >> 1, wh = w & 1;
    const int t4 = lane >> 2, c4 = lane & 3;

    const int kbA = tid & 3, pA = (tid >> 2) & 63;
    const int m1  = ((pA >> 3) << 4) + (pA & 7);
    const int ccq = (tid >> 8) * 2;
    const int dV  = tid & 127, kbV0 = (tid >> 7) & 3;

    const int c_base = (c4 & 1) * 2;
    const int c_hi   = (c4 >> 1) * 2;

    // ---- stage Q once (A-frag layout, tf32) ----
    {
        const float* a1p = qkv + (size_t)(bi * 128 + m1) * QKV3 + h * HSTRIDE;
        const float* a2p = a1p + (size_t)8 * QKV3;
#pragma unroll
        for (int u = 0; u < 2; u++) {
            int cc = ccq + u;
            const float* p1 = a1p + cc * 32 + kbA * 8;
            const float* p2 = a2p + cc * 32 + kbA * 8;
            float4 x0 = *(const float4*)p1, x1 = *(const float4*)(p1 + 4);
            float4 y0 = *(const float4*)p2, y1 = *(const float4*)(p2 + 4);
            int kb = cc * 4 + kbA;
            Qs[kb][pA][0] = make_float4(to_tf32(x0.x), to_tf32(y0.x), to_tf32(x1.x), to_tf32(y1.x));
            Qs[kb][pA][1] = make_float4(to_tf32(x0.y), to_tf32(y0.y), to_tf32(x1.y), to_tf32(y1.y));
            Qs[kb][pA][2] = make_float4(to_tf32(x0.z), to_tf32(y0.z), to_tf32(x1.z), to_tf32(y1.z));
            Qs[kb][pA][3] = make_float4(to_tf32(x0.w), to_tf32(y0.w), to_tf32(x1.w), to_tf32(y1.w));
        }
    }

    float o[8][4];
    float m_run[2] = { -1e30f, -1e30f };
    float l_run[2] = { 0.f, 0.f };
#pragma unroll
    for (int nt = 0; nt < 8; nt++)
#pragma unroll
        for (int r = 0; r < 4; r++) o[nt][r] = 0.f;

    const float scale = 0.08838834764831845f;   // 1/sqrt(128)
    const int r_lo = wr * 16 + t4;
    const int r_hi = r_lo + 8;

    for (int bj = 0; bj <= bi; bj++) {
        // ---- stage K ----
        {
            const float* b1p = qkv + (size_t)(bj * 128 + pA) * QKV3 + h * HSTRIDE + HD;
            const float* b2p = b1p + (size_t)64 * QKV3;
#pragma unroll
            for (int u = 0; u < 2; u++) {
                int cc = ccq + u;
                const float* p1 = b1p + cc * 32 + kbA * 8;
                const float* p2 = b2p + cc * 32 + kbA * 8;
                float4 u0 = *(const float4*)p1, u1 = *(const float4*)(p1 + 4);
                float4 v0 = *(const float4*)p2, v1 = *(const float4*)(p2 + 4);
                int kb = cc * 4 + kbA;
                Ks[kb][pA][0]      = make_float2(to_tf32(u0.x), to_tf32(u1.x));
                Ks[kb][pA][1]      = make_float2(to_tf32(u0.y), to_tf32(u1.y));
                Ks[kb][pA][2]      = make_float2(to_tf32(u0.z), to_tf32(u1.z));
                Ks[kb][pA][3]      = make_float2(to_tf32(u0.w), to_tf32(u1.w));
                Ks[kb][pA + 64][0] = make_float2(to_tf32(v0.x), to_tf32(v1.x));
                Ks[kb][pA + 64][1] = make_float2(to_tf32(v0.y), to_tf32(v1.y));
                Ks[kb][pA + 64][2] = make_float2(to_tf32(v0.z), to_tf32(v1.z));
                Ks[kb][pA + 64][3] = make_float2(to_tf32(v0.w), to_tf32(v1.w));
            }
        }
        // ---- stage V (transposed) ----
        {
            const float* vcol = qkv + (size_t)(bj * 128) * QKV3 + h * HSTRIDE + 2 * HD + dV;
#pragma unroll
            for (int g = 0; g < 4; g++) {
                int kb = g * 4 + kbV0;
                float vv[8];
#pragma unroll
                for (int c = 0; c < 8; c++)
                    vv[c] = vcol[(size_t)(kb * 8 + c) * QKV3];
                Vs[kb][dV][0] = make_float2(to_tf32(vv[0]), to_tf32(vv[4]));
                Vs[kb][dV][1] = make_float2(to_tf32(vv[1]), to_tf32(vv[5]));
                Vs[kb][dV][2] = make_float2(to_tf32(vv[2]), to_tf32(vv[6]));
                Vs[kb][dV][3] = make_float2(to_tf32(vv[3]), to_tf32(vv[7]));
            }
        }
        __syncthreads();   // [S] staging visible

        // ---- Q @ K^T ----
        float sc[8][4];
#pragma unroll
        for (int nt = 0; nt < 8; nt++)
#pragma unroll
            for (int r = 0; r < 4; r++) sc[nt][r] = 0.f;

#pragma unroll
        for (int kb = 0; kb < 16; kb++) {
            float4 af = Qs[kb][wr * 8 + t4][c4];
#pragma unroll
            for (int nt = 0; nt < 8; nt++) {
                float2 bf = Ks[kb][wh * 64 + nt * 8 + t4][c4];
                mma8(sc[nt], af, bf);
            }
        }

        // ---- scale + causal mask ----
        if (bj == bi) {
#pragma unroll
            for (int nt = 0; nt < 8; nt++) {
                int cc = wh * 64 + nt * 8 + 2 * c4;
                sc[nt][0] = (cc     <= r_lo) ? sc[nt][0] * scale : -1e30f;
                sc[nt][1] = (cc + 1 <= r_lo) ? sc[nt][1] * scale : -1e30f;
                sc[nt][2] = (cc     <= r_hi) ? sc[nt][2] * scale : -1e30f;
                sc[nt][3] = (cc + 1 <= r_hi) ? sc[nt][3] * scale : -1e30f;
            }
        } else {
#pragma unroll
            for (int nt = 0; nt < 8; nt++)
#pragma unroll
                for (int r = 0; r < 4; r++) sc[nt][r] *= scale;
        }

        // ---- half-row max -> smem exchange ----
        float p0 = -1e30f, p1 = -1e30f;
#pragma unroll
        for (int nt = 0; nt < 8; nt++) {
            p0 = fmaxf(p0, fmaxf(sc[nt][0], sc[nt][1]));
            p1 = fmaxf(p1, fmaxf(sc[nt][2], sc[nt][3]));
        }
#pragma unroll
        for (int off = 1; off <= 2; off <<= 1) {
            p0 = fmaxf(p0, __shfl_xor_sync(0xffffffffu, p0, off));
            p1 = fmaxf(p1, __shfl_xor_sync(0xffffffffu, p1, off));
        }
        if (c4 == 0) {
            red_m[r_lo][wh] = p0;
            red_m[r_hi][wh] = p1;
        }
        __syncthreads();   // [A] QK reads done + max partials visible

        float M0 = fmaxf(red_m[r_lo][0], red_m[r_lo][1]);
        float M1 = fmaxf(red_m[r_hi][0], red_m[r_hi][1]);
        float mn0 = fmaxf(m_run[0], M0);
        float mn1 = fmaxf(m_run[1], M1);
        float a0 = __expf(m_run[0] - mn0);
        float a1 = __expf(m_run[1] - mn1);
        m_run[0] = mn0;  m_run[1] = mn1;

        // ---- exp + half-row sums ----
        float s0 = 0.f, s1 = 0.f;
#pragma unroll
        for (int nt = 0; nt < 8; nt++) {
            sc[nt][0] = __expf(sc[nt][0] - mn0);
            sc[nt][1] = __expf(sc[nt][1] - mn0);
            sc[nt][2] = __expf(sc[nt][2] - mn1);
            sc[nt][3] = __expf(sc[nt][3] - mn1);
            s0 += sc[nt][0] + sc[nt][1];
            s1 += sc[nt][2] + sc[nt][3];
        }
#pragma unroll
        for (int off = 1; off <= 2; off <<= 1) {
            s0 += __shfl_xor_sync(0xffffffffu, s0, off);
            s1 += __shfl_xor_sync(0xffffffffu, s1, off);
        }
        if (c4 == 0) {
            red_s[r_lo][wh] = s0;
            red_s[r_hi][wh] = s1;
        }

        // ---- write P (tf32) into Pp (= Ks region, free after [A]) ----
#pragma unroll
        for (int nt = 0; nt < 8; nt++) {
            int kb = wh * 8 + nt;
            float* s0p = ((float*)&Pp[wr][kb][t4][c_base]) + c_hi;
            s0p[0] = to_tf32(sc[nt][0]);
            s0p[1] = to_tf32(sc[nt][2]);
            float* s1p = ((float*)&Pp[wr][kb][t4][c_base + 1]) + c_hi;
            s1p[0] = to_tf32(sc[nt][1]);
            s1p[1] = to_tf32(sc[nt][3]);
        }
        __syncthreads();   // [B] P + sum partials visible

        float ts0 = red_s[r_lo][0] + red_s[r_lo][1];
        float ts1 = red_s[r_hi][0] + red_s[r_hi][1];
        l_run[0] = l_run[0] * a0 + ts0;
        l_run[1] = l_run[1] * a1 + ts1;

#pragma unroll
        for (int nt = 0; nt < 8; nt++) {
            o[nt][0] *= a0;  o[nt][1] *= a0;
            o[nt][2] *= a1;  o[nt][3] *= a1;
        }

        // ---- P @ V ----
#pragma unroll
        for (int kb = 0; kb < 16; kb++) {
            float4 af = Pp[wr][kb][t4][c4];
#pragma unroll
            for (int nt = 0; nt < 8; nt++) {
                float2 bf = Vs[kb][wh * 64 + nt * 8 + t4][c4];
                mma8(o[nt], af, bf);
            }
        }
        __syncthreads();   // [C] reads done before next staging
    }

    // ---- epilogue ----
    float inv0 = 1.0f / l_run[0];
    float inv1 = 1.0f / l_run[1];
    int row = bi * 128 + wr * 16 + t4;
#pragma unroll
    for (int nt = 0; nt < 8; nt++) {
        int col = h * HD + wh * 64 + nt * 8 + 2 * c4;
        *(float2*)&ctx[(size_t)row * Hdim + col] =
            make_float2(o[nt][0] * inv0, o[nt][1] * inv0);
        *(float2*)&ctx[(size_t)(row + 8) * Hdim + col] =
            make_float2(o[nt][2] * inv1, o[nt][3] * inv1);
    }
}

// ---------------------------------------------------------------------------
// Launch
// ---------------------------------------------------------------------------
extern "C" void kernel_launch(void* const* d_in, const int* in_sizes, int n_in,
                              void* d_out, int out_size)
{
    const float* hidden  = (const float*)d_in[0];
    // d_in[1] = attention_mask (causal; structure known, unused)
    const float* W_qkv   = (const float*)d_in[2];
    const float* b_qkv   = (const float*)d_in[3];
    const float* W_dense = (const float*)d_in[4];
    const float* b_dense = (const float*)d_in[5];
    float* out = (float*)d_out;

    float *qkv, *ctx;
    cudaGetSymbolAddress((void**)&qkv, g_qkv);
    cudaGetSymbolAddress((void**)&ctx, g_ctx);

    // 1) QKV GEMM: [2048,4096] x [12288,4096]^T -> [2048,12288]
    {
        dim3 grid(QKV3 / 256, S / 128);
        gemm_fp16<<<grid, 256>>>(hidden, W_qkv, b_qkv, qkv,
                                 Hdim, Hdim, Hdim, QKV3);
    }

    // 2) RoPE in place on q,k
    {
        int total = S * NH * 16 * 2;
        rope_kernel<<<(total + 255) / 256, 256>>>(qkv);
    }

    // 3-5) Fused flash attention v4 -> ctx [2048, 4096]
    {
        const int smem_bytes = 194 * 1024;
        cudaFuncSetAttribute(flash4, cudaFuncAttributeMaxDynamicSharedMemorySize,
                             smem_bytes);
        dim3 grid(S / 128, NH);
        flash4<<<grid, 512, smem_bytes>>>(qkv, ctx);
    }

    // 6) Dense GEMM: ctx [2048,4096] x W_dense^T -> out
    {
        dim3 grid(Hdim / 256, S / 128);
        gemm_fp16<<<grid, 256>>>(ctx, W_dense, b_dense, out,
                                 Hdim, Hdim, Hdim, Hdim);
    }
}

// round 14
// speedup vs baseline: 1.4956x; 1.3465x over previous
#include <cuda_runtime.h>
#include <cuda_fp16.h>
#include <cstdint>
#include <math.h>

// Problem constants
#define S    2048
#define Hdim 4096
#define NH   32
#define HD   128
#define QKV3 12288            // 3*Hdim
#define HSTRIDE 384           // 3*HD per head inside a qkv row

// Scratch (device globals; no runtime allocation)
__device__ float g_qkv[(size_t)S * QKV3];            // 100 MB
__device__ float g_ctx[(size_t)S * Hdim];            // 33 MB

// ---------------------------------------------------------------------------
// helpers
// ---------------------------------------------------------------------------
__device__ __forceinline__ float to_tf32(float x) {
    unsigned r;
    asm("cvt.rna.tf32.f32 %0, %1;" : "=r"(r) : "f"(x));
    return __uint_as_float(r);
}

__device__ __forceinline__ uint32_t f2h2(float a, float b) {
    __half2 h = __floats2half2_rn(a, b);
    return *reinterpret_cast<uint32_t*>(&h);
}

// tf32 m16n8k8 (used by flash4 only)
__device__ __forceinline__ void mma8(float c[4], const float4& a, const float2& b) {
    asm volatile(
        "mma.sync.aligned.m16n8k8.row.col.f32.tf32.tf32.f32 "
        "{%0,%1,%2,%3},{%4,%5,%6,%7},{%8,%9},{%0,%1,%2,%3};\n"
        : "+f"(c[0]), "+f"(c[1]), "+f"(c[2]), "+f"(c[3])
        : "r"(__float_as_uint(a.x)), "r"(__float_as_uint(a.y)),
          "r"(__float_as_uint(a.z)), "r"(__float_as_uint(a.w)),
          "r"(__float_as_uint(b.x)), "r"(__float_as_uint(b.y)));
}

// fp16 m16n8k16 (GEMMs)
__device__ __forceinline__ void mma16(float c[4], const uint4& a, const uint2& b) {
    asm volatile(
        "mma.sync.aligned.m16n8k16.row.col.f32.f16.f16.f32 "
        "{%0,%1,%2,%3},{%4,%5,%6,%7},{%8,%9},{%0,%1,%2,%3};\n"
        : "+f"(c[0]), "+f"(c[1]), "+f"(c[2]), "+f"(c[3])
        : "r"(a.x), "r"(a.y), "r"(a.z), "r"(a.w),
          "r"(b.x), "r"(b.y));
}

// ---------------------------------------------------------------------------
// NT GEMM fp16 v2: 512 threads / 16 warps, block 128(M) x 256(N), BK=32.
// Warp grid 2(M) x 8(N), warp tile 64x32, acc fp32 (64 regs).
// Fragment smem layouts (k-pair space, kp = k/2):
//  Ah[kb][p][c] : uint4 = (h2 A[m1][kp=c], h2 A[m1+8][c], h2 A[m1][c+4], h2 A[m1+8][c+4])
//                 m1 = ((p>>3)<<4)+(p&7), kp local to the kb-block of 8 pairs
//  Bh[kb][n][c] : uint2 = (h2 B[n][kp=c], h2 B[n][kp=c+4])
// ---------------------------------------------------------------------------
__global__ __launch_bounds__(512, 1) void gemm_fp16(
    const float* __restrict__ A, const float* __restrict__ B,
    const float* __restrict__ bias, float* __restrict__ C,
    int K, int lda, int ldb, int ldc)
{
    __shared__ uint4 Ah[2][64][4];    // 8 KB
    __shared__ uint2 Bh[2][256][4];   // 16 KB

    const int tid = threadIdx.x, lane = tid & 31, wid = tid >> 5;
    const int warp_m = wid & 1, warp_n = wid >> 1;   // 2 x 8 warps
    const int t4 = lane >> 2, c4 = lane & 3;

    // ---- A loader: 512 threads, each 2 float4 (rows m1, m1+8; 4 k-elems) ----
    const int pA  = tid >> 3;                 // 0..63
    const int r3  = tid & 7;
    const int hsA = r3 & 1;                   // which half of the uint4 (byte off 8*hsA)
    const int kbhA= (r3 >> 1) & 1;            // 16-elem block
    const int ihA = r3 >> 2;                  // 0..1 -> entries i = 2*ihA, 2*ihA+1
    const int m1  = ((pA >> 3) << 4) + (pA & 7);
    const int kA  = kbhA * 16 + hsA * 8 + ihA * 4;

    // ---- B loader: 512 threads, each half a row (16 k-elems) ----
    const int nB  = tid >> 1;                 // 0..255
    const int hbB = tid & 1;                  // kb block

    const float* a1p = A + (size_t)(blockIdx.y * 128 + m1) * lda + kA;
    const float* a2p = a1p + (size_t)8 * lda;
    const float* Bp  = B + (size_t)(blockIdx.x * 256 + nB) * ldb + hbB * 16;

    float acc[4][4][4];
#pragma unroll
    for (int i = 0; i < 4; i++)
#pragma unroll
        for (int j = 0; j < 4; j++)
#pragma unroll
            for (int r = 0; r < 4; r++) acc[i][j][r] = 0.f;

    float4 xa, ya;            // A prefetch: rows m1 / m1+8, 4 elems
    float4 bu[4];             // B prefetch: 16 elems
    xa = *(const float4*)(a1p);
    ya = *(const float4*)(a2p);
#pragma unroll
    for (int i = 0; i < 4; i++) bu[i] = *(const float4*)(Bp + i * 4);

    for (int k0 = 0; k0 < K; k0 += 32) {
        __syncthreads();   // previous mma reads done

        // ---- A: 2 uint2 halves (entries i = 2*ihA, 2*ihA+1) ----
        {
            float xs[4] = { xa.x, xa.y, xa.z, xa.w };
            float ys[4] = { ya.x, ya.y, ya.z, ya.w };
#pragma unroll
            for (int j = 0; j < 2; j++) {
                uint32_t lo = f2h2(xs[2 * j], xs[2 * j + 1]);
                uint32_t hi = f2h2(ys[2 * j], ys[2 * j + 1]);
                *(uint2*)((char*)(&Ah[kbhA][pA][ihA * 2 + j]) + hsA * 8) =
                    make_uint2(lo, hi);
            }
        }
        // ---- B: 4 uint2 for half-row (nB, kb=hbB) ----
        Bh[hbB][nB][0] = make_uint2(f2h2(bu[0].x, bu[0].y), f2h2(bu[2].x, bu[2].y));
        Bh[hbB][nB][1] = make_uint2(f2h2(bu[0].z, bu[0].w), f2h2(bu[2].z, bu[2].w));
        Bh[hbB][nB][2] = make_uint2(f2h2(bu[1].x, bu[1].y), f2h2(bu[3].x, bu[3].y));
        Bh[hbB][nB][3] = make_uint2(f2h2(bu[1].z, bu[1].w), f2h2(bu[3].z, bu[3].w));
        __syncthreads();   // chunk staged

        // ---- prefetch next chunk (overlaps mma) ----
        int kn = k0 + 32;
        if (kn < K) {
            xa = *(const float4*)(a1p + kn);
            ya = *(const float4*)(a2p + kn);
#pragma unroll
            for (int i = 0; i < 4; i++) bu[i] = *(const float4*)(Bp + kn + i * 4);
        }

        // ---- mma: 2 kb-blocks x 16 mma16 ----
#pragma unroll
        for (int kb = 0; kb < 2; kb++) {
            uint4 af[4]; uint2 bf[4];
#pragma unroll
            for (int mt = 0; mt < 4; mt++)
                af[mt] = Ah[kb][((warp_m * 4 + mt) << 3) + t4][c4];
#pragma unroll
            for (int nt = 0; nt < 4; nt++)
                bf[nt] = Bh[kb][warp_n * 32 + nt * 8 + t4][c4];
#pragma unroll
            for (int mt = 0; mt < 4; mt++)
#pragma unroll
                for (int nt = 0; nt < 4; nt++) mma16(acc[mt][nt], af[mt], bf[nt]);
        }
    }

#pragma unroll
    for (int mt = 0; mt < 4; mt++) {
        int r0 = blockIdx.y * 128 + warp_m * 64 + mt * 16 + t4;
#pragma unroll
        for (int nt = 0; nt < 4; nt++) {
            int cc = blockIdx.x * 256 + warp_n * 32 + nt * 8 + 2 * c4;
            float b0 = bias[cc], b1 = bias[cc + 1];
            *(float2*)&C[(size_t)r0 * ldc + cc] =
                make_float2(acc[mt][nt][0] + b0, acc[mt][nt][1] + b1);
            *(float2*)&C[(size_t)(r0 + 8) * ldc + cc] =
                make_float2(acc[mt][nt][2] + b0, acc[mt][nt][3] + b1);
        }
    }
}

// ---------------------------------------------------------------------------
// RoPE (in place on q,k slices of g_qkv)
// ---------------------------------------------------------------------------
__global__ void rope_kernel(float* __restrict__ qkv)
{
    int idx = blockIdx.x * blockDim.x + threadIdx.x;
    const int total = S * NH * 16 * 2;
    if (idx >= total) return;

    int i = idx & 15;
    int r = idx >> 4;
    int h = r & 31;
    r >>= 5;
    int which = r & 1;
    int s = r >> 1;

    float inv = powf(10000.0f, -(float)i / 16.0f);
    float ang = (float)s * inv;
    float c, sn;
    sincosf(ang, &sn, &c);

    float* base = qkv + (size_t)s * QKV3 + h * HSTRIDE + which * HD;
    float x1 = base[i];
    float x2 = base[i + 16];
    base[i]      = x1 * c - x2 * sn;
    base[i + 16] = x2 * c + x1 * sn;
}

// ---------------------------------------------------------------------------
// Flash attention v4 (proven, ~170us): 512 threads / 16 warps. tf32 path.
// ---------------------------------------------------------------------------
__global__ __launch_bounds__(512, 1) void flash4(
    const float* __restrict__ qkv, float* __restrict__ ctx)
{
    extern __shared__ char smbase[];
    float4 (*Qs)[64][4]    = (float4 (*)[64][4])(smbase);              // [16][64][4]
    float2 (*Ks)[128][4]   = (float2 (*)[128][4])(smbase + 65536);     // [16][128][4]
    float4 (*Pp)[16][8][4] = (float4 (*)[16][8][4])(smbase + 65536);   // alias of Ks
    float2 (*Vs)[128][4]   = (float2 (*)[128][4])(smbase + 131072);    // [16][128][4]
    float  (*red_m)[2]     = (float (*)[2])(smbase + 196608);          // [128][2]
    float  (*red_s)[2]     = (float (*)[2])(smbase + 197632);          // [128][2]

    const int bi = (int)(gridDim.x - 1 - blockIdx.x);   // heavy tiles first
    const int h  = blockIdx.y;

    const int tid = threadIdx.x, lane = tid & 31, w = tid >> 5;
    const int wr = w >> 1, wh = w & 1;
    const int t4 = lane >> 2, c4 = lane & 3;

    const int kbA = tid & 3, pA = (tid >> 2) & 63;
    const int m1  = ((pA >> 3) << 4) + (pA & 7);
    const int ccq = (tid >> 8) * 2;
    const int dV  = tid & 127, kbV0 = (tid >> 7) & 3;

    const int c_base = (c4 & 1) * 2;
    const int c_hi   = (c4 >> 1) * 2;

    // ---- stage Q once (A-frag layout, tf32) ----
    {
        const float* a1p = qkv + (size_t)(bi * 128 + m1) * QKV3 + h * HSTRIDE;
        const float* a2p = a1p + (size_t)8 * QKV3;
#pragma unroll
        for (int u = 0; u < 2; u++) {
            int cc = ccq + u;
            const float* p1 = a1p + cc * 32 + kbA * 8;
            const float* p2 = a2p + cc * 32 + kbA * 8;
            float4 x0 = *(const float4*)p1, x1 = *(const float4*)(p1 + 4);
            float4 y0 = *(const float4*)p2, y1 = *(const float4*)(p2 + 4);
            int kb = cc * 4 + kbA;
            Qs[kb][pA][0] = make_float4(to_tf32(x0.x), to_tf32(y0.x), to_tf32(x1.x), to_tf32(y1.x));
            Qs[kb][pA][1] = make_float4(to_tf32(x0.y), to_tf32(y0.y), to_tf32(x1.y), to_tf32(y1.y));
            Qs[kb][pA][2] = make_float4(to_tf32(x0.z), to_tf32(y0.z), to_tf32(x1.z), to_tf32(y1.z));
            Qs[kb][pA][3] = make_float4(to_tf32(x0.w), to_tf32(y0.w), to_tf32(x1.w), to_tf32(y1.w));
        }
    }

    float o[8][4];
    float m_run[2] = { -1e30f, -1e30f };
    float l_run[2] = { 0.f, 0.f };
#pragma unroll
    for (int nt = 0; nt < 8; nt++)
#pragma unroll
        for (int r = 0; r < 4; r++) o[nt][r] = 0.f;

    const float scale = 0.08838834764831845f;   // 1/sqrt(128)
    const int r_lo = wr * 16 + t4;
    const int r_hi = r_lo + 8;

    for (int bj = 0; bj <= bi; bj++) {
        // ---- stage K ----
        {
            const float* b1p = qkv + (size_t)(bj * 128 + pA) * QKV3 + h * HSTRIDE + HD;
            const float* b2p = b1p + (size_t)64 * QKV3;
#pragma unroll
            for (int u = 0; u < 2; u++) {
                int cc = ccq + u;
                const float* p1 = b1p + cc * 32 + kbA * 8;
                const float* p2 = b2p + cc * 32 + kbA * 8;
                float4 u0 = *(const float4*)p1, u1 = *(const float4*)(p1 + 4);
                float4 v0 = *(const float4*)p2, v1 = *(const float4*)(p2 + 4);
                int kb = cc * 4 + kbA;
                Ks[kb][pA][0]      = make_float2(to_tf32(u0.x), to_tf32(u1.x));
                Ks[kb][pA][1]      = make_float2(to_tf32(u0.y), to_tf32(u1.y));
                Ks[kb][pA][2]      = make_float2(to_tf32(u0.z), to_tf32(u1.z));
                Ks[kb][pA][3]      = make_float2(to_tf32(u0.w), to_tf32(u1.w));
                Ks[kb][pA + 64][0] = make_float2(to_tf32(v0.x), to_tf32(v1.x));
                Ks[kb][pA + 64][1] = make_float2(to_tf32(v0.y), to_tf32(v1.y));
                Ks[kb][pA + 64][2] = make_float2(to_tf32(v0.z), to_tf32(v1.z));
                Ks[kb][pA + 64][3] = make_float2(to_tf32(v0.w), to_tf32(v1.w));
            }
        }
        // ---- stage V (transposed) ----
        {
            const float* vcol = qkv + (size_t)(bj * 128) * QKV3 + h * HSTRIDE + 2 * HD + dV;
#pragma unroll
            for (int g = 0; g < 4; g++) {
                int kb = g * 4 + kbV0;
                float vv[8];
#pragma unroll
                for (int c = 0; c < 8; c++)
                    vv[c] = vcol[(size_t)(kb * 8 + c) * QKV3];
                Vs[kb][dV][0] = make_float2(to_tf32(vv[0]), to_tf32(vv[4]));
                Vs[kb][dV][1] = make_float2(to_tf32(vv[1]), to_tf32(vv[5]));
                Vs[kb][dV][2] = make_float2(to_tf32(vv[2]), to_tf32(vv[6]));
                Vs[kb][dV][3] = make_float2(to_tf32(vv[3]), to_tf32(vv[7]));
            }
        }
        __syncthreads();   // [S] staging visible

        // ---- Q @ K^T ----
        float sc[8][4];
#pragma unroll
        for (int nt = 0; nt < 8; nt++)
#pragma unroll
            for (int r = 0; r < 4; r++) sc[nt][r] = 0.f;

#pragma unroll
        for (int kb = 0; kb < 16; kb++) {
            float4 af = Qs[kb][wr * 8 + t4][c4];
#pragma unroll
            for (int nt = 0; nt < 8; nt++) {
                float2 bf = Ks[kb][wh * 64 + nt * 8 + t4][c4];
                mma8(sc[nt], af, bf);
            }
        }

        // ---- scale + causal mask ----
        if (bj == bi) {
#pragma unroll
            for (int nt = 0; nt < 8; nt++) {
                int cc = wh * 64 + nt * 8 + 2 * c4;
                sc[nt][0] = (cc     <= r_lo) ? sc[nt][0] * scale : -1e30f;
                sc[nt][1] = (cc + 1 <= r_lo) ? sc[nt][1] * scale : -1e30f;
                sc[nt][2] = (cc     <= r_hi) ? sc[nt][2] * scale : -1e30f;
                sc[nt][3] = (cc + 1 <= r_hi) ? sc[nt][3] * scale : -1e30f;
            }
        } else {
#pragma unroll
            for (int nt = 0; nt < 8; nt++)
#pragma unroll
                for (int r = 0; r < 4; r++) sc[nt][r] *= scale;
        }

        // ---- half-row max -> smem exchange ----
        float p0 = -1e30f, p1 = -1e30f;
#pragma unroll
        for (int nt = 0; nt < 8; nt++) {
            p0 = fmaxf(p0, fmaxf(sc[nt][0], sc[nt][1]));
            p1 = fmaxf(p1, fmaxf(sc[nt][2], sc[nt][3]));
        }
#pragma unroll
        for (int off = 1; off <= 2; off <<= 1) {
            p0 = fmaxf(p0, __shfl_xor_sync(0xffffffffu, p0, off));
            p1 = fmaxf(p1, __shfl_xor_sync(0xffffffffu, p1, off));
        }
        if (c4 == 0) {
            red_m[r_lo][wh] = p0;
            red_m[r_hi][wh] = p1;
        }
        __syncthreads();   // [A] QK reads done + max partials visible

        float M0 = fmaxf(red_m[r_lo][0], red_m[r_lo][1]);
        float M1 = fmaxf(red_m[r_hi][0], red_m[r_hi][1]);
        float mn0 = fmaxf(m_run[0], M0);
        float mn1 = fmaxf(m_run[1], M1);
        float a0 = __expf(m_run[0] - mn0);
        float a1 = __expf(m_run[1] - mn1);
        m_run[0] = mn0;  m_run[1] = mn1;

        // ---- exp + half-row sums ----
        float s0 = 0.f, s1 = 0.f;
#pragma unroll
        for (int nt = 0; nt < 8; nt++) {
            sc[nt][0] = __expf(sc[nt][0] - mn0);
            sc[nt][1] = __expf(sc[nt][1] - mn0);
            sc[nt][2] = __expf(sc[nt][2] - mn1);
            sc[nt][3] = __expf(sc[nt][3] - mn1);
            s0 += sc[nt][0] + sc[nt][1];
            s1 += sc[nt][2] + sc[nt][3];
        }
#pragma unroll
        for (int off = 1; off <= 2; off <<= 1) {
            s0 += __shfl_xor_sync(0xffffffffu, s0, off);
            s1 += __shfl_xor_sync(0xffffffffu, s1, off);
        }
        if (c4 == 0) {
            red_s[r_lo][wh] = s0;
            red_s[r_hi][wh] = s1;
        }

        // ---- write P (tf32) into Pp (= Ks region, free after [A]) ----
#pragma unroll
        for (int nt = 0; nt < 8; nt++) {
            int kb = wh * 8 + nt;
            float* s0p = ((float*)&Pp[wr][kb][t4][c_base]) + c_hi;
            s0p[0] = to_tf32(sc[nt][0]);
            s0p[1] = to_tf32(sc[nt][2]);
            float* s1p = ((float*)&Pp[wr][kb][t4][c_base + 1]) + c_hi;
            s1p[0] = to_tf32(sc[nt][1]);
            s1p[1] = to_tf32(sc[nt][3]);
        }
        __syncthreads();   // [B] P + sum partials visible

        float ts0 = red_s[r_lo][0] + red_s[r_lo][1];
        float ts1 = red_s[r_hi][0] + red_s[r_hi][1];
        l_run[0] = l_run[0] * a0 + ts0;
        l_run[1] = l_run[1] * a1 + ts1;

#pragma unroll
        for (int nt = 0; nt < 8; nt++) {
            o[nt][0] *= a0;  o[nt][1] *= a0;
            o[nt][2] *= a1;  o[nt][3] *= a1;
        }

        // ---- P @ V ----
#pragma unroll
        for (int kb = 0; kb < 16; kb++) {
            float4 af = Pp[wr][kb][t4][c4];
#pragma unroll
            for (int nt = 0; nt < 8; nt++) {
                float2 bf = Vs[kb][wh * 64 + nt * 8 + t4][c4];
                mma8(o[nt], af, bf);
            }
        }
        __syncthreads();   // [C] reads done before next staging
    }

    // ---- epilogue ----
    float inv0 = 1.0f / l_run[0];
    float inv1 = 1.0f / l_run[1];
    int row = bi * 128 + wr * 16 + t4;
#pragma unroll
    for (int nt = 0; nt < 8; nt++) {
        int col = h * HD + wh * 64 + nt * 8 + 2 * c4;
        *(float2*)&ctx[(size_t)row * Hdim + col] =
            make_float2(o[nt][0] * inv0, o[nt][1] * inv0);
        *(float2*)&ctx[(size_t)(row + 8) * Hdim + col] =
            make_float2(o[nt][2] * inv1, o[nt][3] * inv1);
    }
}

// ---------------------------------------------------------------------------
// Launch
// ---------------------------------------------------------------------------
extern "C" void kernel_launch(void* const* d_in, const int* in_sizes, int n_in,
                              void* d_out, int out_size)
{
    const float* hidden  = (const float*)d_in[0];
    // d_in[1] = attention_mask (causal; structure known, unused)
    const float* W_qkv   = (const float*)d_in[2];
    const float* b_qkv   = (const float*)d_in[3];
    const float* W_dense = (const float*)d_in[4];
    const float* b_dense = (const float*)d_in[5];
    float* out = (float*)d_out;

    float *qkv, *ctx;
    cudaGetSymbolAddress((void**)&qkv, g_qkv);
    cudaGetSymbolAddress((void**)&ctx, g_ctx);

    // 1) QKV GEMM: [2048,4096] x [12288,4096]^T -> [2048,12288]
    {
        dim3 grid(QKV3 / 256, S / 128);
        gemm_fp16<<<grid, 512>>>(hidden, W_qkv, b_qkv, qkv,
                                 Hdim, Hdim, Hdim, QKV3);
    }

    // 2) RoPE in place on q,k
    {
        int total = S * NH * 16 * 2;
        rope_kernel<<<(total + 255) / 256, 256>>>(qkv);
    }

    // 3-5) Fused flash attention v4 -> ctx [2048, 4096]
    {
        const int smem_bytes = 194 * 1024;
        cudaFuncSetAttribute(flash4, cudaFuncAttributeMaxDynamicSharedMemorySize,
                             smem_bytes);
        dim3 grid(S / 128, NH);
        flash4<<<grid, 512, smem_bytes>>>(qkv, ctx);
    }

    // 6) Dense GEMM: ctx [2048,4096] x W_dense^T -> out
    {
        dim3 grid(Hdim / 256, S / 128);
        gemm_fp16<<<grid, 512>>>(ctx, W_dense, b_dense, out,
                                 Hdim, Hdim, Hdim, Hdim);
    }
}